// round 17
// baseline (speedup 1.0000x reference)
#include <cuda_runtime.h>

#define N_NODES 50000
#define N_EDGES 800000
#define IN_F    128
#define OUT_F   64
#define NEG_SLOPE 0.2f
#define MAXDEG  128   // deg ~ Poisson(16); max over 50K nodes ~50. Huge margin.
#define RPB     128   // gemm rows per block
#define GT      256   // gemm threads per block (8 warps, 16 rows/warp)

// ---------------- scratch (static device globals; no allocs) ----------------
__device__ float g_h[(size_t)N_NODES * OUT_F];          // 12.8 MB
__device__ float g_asrc[N_NODES];
__device__ float g_adst[N_NODES];
__device__ float g_wa[IN_F];
__device__ float g_wd[IN_F];
__device__ int   g_count[N_NODES];
__device__ int   g_slots[(size_t)N_NODES * MAXDEG];     // src ids, 25.6 MB
__device__ int   g_is64;

// ---------------- K0: zero counts + detect dtype (side stream) --------------
// int64 LE: every odd 32-bit word is 0 (ids in [0,50000)). int32: odd words
// are node ids; 1024 consecutive zeros is ~impossible.
__global__ void k_init(const unsigned int* __restrict__ w) {
    int t = blockIdx.x * blockDim.x + threadIdx.x;
    if (t < N_NODES) g_count[t] = 0;
    if (blockIdx.x == 0) {
        int nz = 0;
        #pragma unroll
        for (int j = 0; j < 4; j++)
            nz |= (w[2 * (threadIdx.x + 256 * j) + 1] != 0u) ? 1 : 0;
        int any = __syncthreads_or(nz);
        if (threadIdx.x == 0) g_is64 = any ? 0 : 1;
    }
}

// ---------------- K0b: wa = W @ att_src, wd = W @ att_dst (1 block) ---------
__global__ void k_wa(const float* __restrict__ W,
                     const float* __restrict__ att_src,
                     const float* __restrict__ att_dst) {
    __shared__ float as[OUT_F], ad[OUT_F];
    int k = threadIdx.x;             // 0..127
    if (k < OUT_F) { as[k] = att_src[k]; ad[k] = att_dst[k]; }
    __syncthreads();
    float sa = 0.f, sd = 0.f;
    const float4* Wr = (const float4*)(W + k * OUT_F);
    #pragma unroll
    for (int n4 = 0; n4 < OUT_F / 4; n4++) {
        float4 w = Wr[n4];
        const float4 a = *(const float4*)&as[4 * n4];
        const float4 d = *(const float4*)&ad[4 * n4];
        sa += w.x * a.x + w.y * a.y + w.z * a.z + w.w * a.w;
        sd += w.x * d.x + w.y * d.y + w.z * d.z + w.w * d.w;
    }
    g_wa[k] = sa;
    g_wd[k] = sd;
}

// ---------------- K0c: asrc/adst = x @ wa, x @ wd (warp per node) -----------
__global__ __launch_bounds__(256) void k_attn(const float* __restrict__ x) {
    int n = (blockIdx.x * blockDim.x + threadIdx.x) >> 5;
    if (n >= N_NODES) return;
    int lane = threadIdx.x & 31;
    float4 xv = ((const float4*)x)[(size_t)n * 32 + lane];
    float4 wa = ((const float4*)g_wa)[lane];
    float4 wd = ((const float4*)g_wd)[lane];
    float s = xv.x * wa.x + xv.y * wa.y + xv.z * wa.z + xv.w * wa.w;
    float d = xv.x * wd.x + xv.y * wd.y + xv.z * wd.z + xv.w * wd.w;
    #pragma unroll
    for (int o = 16; o; o >>= 1) {
        s += __shfl_xor_sync(0xffffffffu, s, o);
        d += __shfl_xor_sync(0xffffffffu, d, o);
    }
    if (lane == 0) { g_asrc[n] = s; g_adst[n] = d; }
}

// ---------------- K1: h = x @ W, 128 rows/block, 4 cols/thread --------------
// R13 inner loop (measured best of 8 gemm variants) with the epilogue
// DELETED: accumulators go straight to g_h via coalesced STG.128 (lanes
// q=0..15 write cols 4q..4q+3 of one row = one 256B segment per half-warp).
// No hs staging, no extra syncs, no attn reduction (done in k_attn via
// the x@(W@att) identity).
__global__ __launch_bounds__(GT) void k_gemm(const float* __restrict__ x,
                                             const float* __restrict__ W) {
    extern __shared__ __align__(16) float sm[];
    float (*xs)[RPB]   = (float (*)[RPB])sm;                  // [128][128] k-major
    float (*Ws)[OUT_F] = (float (*)[OUT_F])(sm + IN_F * RPB); // [128][64]

    const int tx = threadIdx.x;
    const int lane = tx & 31;
    const int warp = tx >> 5;          // 0..7
    const int rbase = blockIdx.x * RPB;

    {   // load W: 2048 float4 / 256 threads
        const float4* W4 = (const float4*)W;
        float4* Ws4 = (float4*)&Ws[0][0];
        #pragma unroll
        for (int i = 0; i < 8; i++) Ws4[tx + GT * i] = W4[tx + GT * i];
    }
    {   // load x tile transposed: 2 threads per row, 16 float4 each
        const int row = tx >> 1;
        const int half = tx & 1;
        const int grow = rbase + row;
        const float4* x4 = (const float4*)x;
        #pragma unroll
        for (int j = 0; j < 16; j++) {
            int k4 = half * 16 + j;
            float4 v = (grow < N_NODES) ? x4[(size_t)grow * (IN_F / 4) + k4]
                                        : make_float4(0.f, 0.f, 0.f, 0.f);
            xs[4 * k4 + 0][row] = v.x;
            xs[4 * k4 + 1][row] = v.y;
            xs[4 * k4 + 2][row] = v.z;
            xs[4 * k4 + 3][row] = v.w;
        }
    }
    __syncthreads();

    const int q  = lane & 15;                 // cols 4q..4q+3
    const int rowbase = warp * 16 + (lane >> 4) * 8;  // 8 rows = 4 pairs
    unsigned long long acc[4][4];             // [pair][col]
    #pragma unroll
    for (int j = 0; j < 4; j++)
        #pragma unroll
        for (int c = 0; c < 4; c++) acc[j][c] = 0ull;

    #pragma unroll 2
    for (int k = 0; k < IN_F; k++) {
        float4 wv = *(const float4*)&Ws[k][4 * q];
        unsigned long long w2[4];
        asm("mov.b64 %0, {%1, %1};" : "=l"(w2[0]) : "r"(__float_as_uint(wv.x)));
        asm("mov.b64 %0, {%1, %1};" : "=l"(w2[1]) : "r"(__float_as_uint(wv.y)));
        asm("mov.b64 %0, {%1, %1};" : "=l"(w2[2]) : "r"(__float_as_uint(wv.z)));
        asm("mov.b64 %0, {%1, %1};" : "=l"(w2[3]) : "r"(__float_as_uint(wv.w)));
        const ulonglong2* xr = (const ulonglong2*)&xs[k][rowbase];
        ulonglong2 qa = xr[0], qb = xr[1];    // broadcast within half
        unsigned long long xp[4] = {qa.x, qa.y, qb.x, qb.y};
        #pragma unroll
        for (int j = 0; j < 4; j++)
            #pragma unroll
            for (int c = 0; c < 4; c++)
                asm("fma.rn.f32x2 %0, %1, %2, %3;"
                    : "=l"(acc[j][c]) : "l"(xp[j]), "l"(w2[c]), "l"(acc[j][c]));
    }

    // direct coalesced epilogue: two STG.128 per row-pair
    #pragma unroll
    for (int j = 0; j < 4; j++) {
        int r0 = rbase + rowbase + 2 * j;
        float4 lo = make_float4(__uint_as_float((unsigned)acc[j][0]),
                                __uint_as_float((unsigned)acc[j][1]),
                                __uint_as_float((unsigned)acc[j][2]),
                                __uint_as_float((unsigned)acc[j][3]));
        float4 hi = make_float4(__uint_as_float((unsigned)(acc[j][0] >> 32)),
                                __uint_as_float((unsigned)(acc[j][1] >> 32)),
                                __uint_as_float((unsigned)(acc[j][2] >> 32)),
                                __uint_as_float((unsigned)(acc[j][3] >> 32)));
        if (r0 < N_NODES)     *(float4*)(g_h + (size_t)r0 * OUT_F + 4 * q) = lo;
        if (r0 + 1 < N_NODES) *(float4*)(g_h + (size_t)(r0 + 1) * OUT_F + 4 * q) = hi;
    }
}

// ---------------- K2: bucket edges by destination, 4 edges/thread -----------
__global__ __launch_bounds__(256) void k_fill(const void* __restrict__ ei) {
    int base = (blockIdx.x * blockDim.x + threadIdx.x) * 4;
    const int* w = (const int*)ei;
    const bool is64 = (g_is64 != 0);

    int s[4], d[4], slot[4];
    #pragma unroll
    for (int j = 0; j < 4; j++) {
        int e = base + j;
        if (e < N_EDGES) {
            if (is64) { s[j] = w[2 * e]; d[j] = w[2 * (N_EDGES + e)]; }
            else      { s[j] = w[e];     d[j] = w[N_EDGES + e]; }
        } else s[j] = -1;
    }
    #pragma unroll
    for (int j = 0; j < 4; j++)
        if (s[j] >= 0) slot[j] = atomicAdd(&g_count[d[j]], 1);
    #pragma unroll
    for (int j = 0; j < 4; j++)
        if (s[j] >= 0 && slot[j] < MAXDEG)
            g_slots[(size_t)d[j] * MAXDEG + slot[j]] = s[j];
}

// ---------------- K3: aggregation — R4 formulation (measured best) ----------
// Warp per node; coalesced 32-slot batch load; 4 subgroups of 8 lanes each
// handle one edge per step. denom is identical across the 8 lanes of a
// subgroup -> reduced ONLY across subgroups (o=8,16).
__global__ __launch_bounds__(256) void k_aggr(const float* __restrict__ bias,
                                              float* __restrict__ out) {
    int n = (blockIdx.x * blockDim.x + threadIdx.x) >> 5;
    if (n >= N_NODES) return;
    const int lane = threadIdx.x & 31;
    const int g8 = lane >> 3;    // edge subgroup 0..3
    const int qi = lane & 7;     // col octet

    int deg = g_count[n];
    deg = deg < MAXDEG ? deg : MAXDEG;
    const float adst_n = g_adst[n];
    const int* slots = g_slots + (size_t)n * MAXDEG;

    float4 a0 = make_float4(0.f, 0.f, 0.f, 0.f);
    float4 a1 = make_float4(0.f, 0.f, 0.f, 0.f);
    float denom = 0.0f;

    for (int base = 0; base < deg; base += 32) {
        int li = base + lane;
        int sv = slots[li < deg ? li : (deg - 1)];   // coalesced batch load
        int m = deg - base;
        #pragma unroll
        for (int j = 0; j < 32; j += 4) {
            if (j >= m) break;
            int idx = j + g8;
            int s = __shfl_sync(0xffffffffu, sv, idx);
            if (idx < m) {
                float e = g_asrc[s] + adst_n;
                e = (e > 0.0f) ? e : NEG_SLOPE * e;
                float p = __expf(e);
                const float4* hp = (const float4*)(g_h + (size_t)s * OUT_F);
                float4 h0 = hp[qi];
                float4 h1 = hp[8 + qi];
                a0.x = fmaf(p, h0.x, a0.x); a0.y = fmaf(p, h0.y, a0.y);
                a0.z = fmaf(p, h0.z, a0.z); a0.w = fmaf(p, h0.w, a0.w);
                a1.x = fmaf(p, h1.x, a1.x); a1.y = fmaf(p, h1.y, a1.y);
                a1.z = fmaf(p, h1.z, a1.z); a1.w = fmaf(p, h1.w, a1.w);
                denom += p;
            }
        }
    }

    // reduce across the 4 subgroups ONLY (lanes differing in bits 3,4)
    #pragma unroll
    for (int o = 8; o <= 16; o <<= 1) {
        a0.x += __shfl_xor_sync(0xffffffffu, a0.x, o);
        a0.y += __shfl_xor_sync(0xffffffffu, a0.y, o);
        a0.z += __shfl_xor_sync(0xffffffffu, a0.z, o);
        a0.w += __shfl_xor_sync(0xffffffffu, a0.w, o);
        a1.x += __shfl_xor_sync(0xffffffffu, a1.x, o);
        a1.y += __shfl_xor_sync(0xffffffffu, a1.y, o);
        a1.z += __shfl_xor_sync(0xffffffffu, a1.z, o);
        a1.w += __shfl_xor_sync(0xffffffffu, a1.w, o);
        denom += __shfl_xor_sync(0xffffffffu, denom, o);
    }

    if (lane < 8) {
        // self loop + epilogue
        float e = g_asrc[n] + adst_n;
        e = (e > 0.0f) ? e : NEG_SLOPE * e;
        float p = __expf(e);
        const float4* hp = (const float4*)(g_h + (size_t)n * OUT_F);
        float4 h0 = hp[qi], h1 = hp[8 + qi];
        a0.x = fmaf(p, h0.x, a0.x); a0.y = fmaf(p, h0.y, a0.y);
        a0.z = fmaf(p, h0.z, a0.z); a0.w = fmaf(p, h0.w, a0.w);
        a1.x = fmaf(p, h1.x, a1.x); a1.y = fmaf(p, h1.y, a1.y);
        a1.z = fmaf(p, h1.z, a1.z); a1.w = fmaf(p, h1.w, a1.w);

        float inv = 1.0f / (denom + p + 1e-16f);
        float4 b0 = ((const float4*)bias)[qi];
        float4 b1 = ((const float4*)bias)[8 + qi];
        float4 o0, o1;
        o0.x = fmaf(a0.x, inv, b0.x); o0.y = fmaf(a0.y, inv, b0.y);
        o0.z = fmaf(a0.z, inv, b0.z); o0.w = fmaf(a0.w, inv, b0.w);
        o1.x = fmaf(a1.x, inv, b1.x); o1.y = fmaf(a1.y, inv, b1.y);
        o1.z = fmaf(a1.z, inv, b1.z); o1.w = fmaf(a1.w, inv, b1.w);
        o0.x = o0.x > 0.f ? o0.x : 0.f; o0.y = o0.y > 0.f ? o0.y : 0.f;
        o0.z = o0.z > 0.f ? o0.z : 0.f; o0.w = o0.w > 0.f ? o0.w : 0.f;
        o1.x = o1.x > 0.f ? o1.x : 0.f; o1.y = o1.y > 0.f ? o1.y : 0.f;
        o1.z = o1.z > 0.f ? o1.z : 0.f; o1.w = o1.w > 0.f ? o1.w : 0.f;
        ((float4*)out)[(size_t)n * 16 + qi]     = o0;
        ((float4*)out)[(size_t)n * 16 + 8 + qi] = o1;
    }
}

// ---------------- launch: fork-join overlap (init/wa/attn/fill || gemm) -----
extern "C" void kernel_launch(void* const* d_in, const int* in_sizes, int n_in,
                              void* d_out, int out_size) {
    const float* x       = (const float*)d_in[0];
    const void*  ei      = d_in[1];
    const float* W       = (const float*)d_in[2];
    const float* att_src = (const float*)d_in[3];
    const float* att_dst = (const float*)d_in[4];
    const float* bias    = (const float*)d_in[5];
    float* out = (float*)d_out;
    (void)in_sizes; (void)n_in; (void)out_size;

    const int GEMM_SMEM = (IN_F * RPB + IN_F * OUT_F) * (int)sizeof(float); // 96 KB

    static cudaStream_t s1 = nullptr;
    static cudaEvent_t ev_fork = nullptr, ev_join = nullptr;
    if (!s1) {
        cudaStreamCreateWithFlags(&s1, cudaStreamNonBlocking);
        cudaEventCreateWithFlags(&ev_fork, cudaEventDisableTiming);
        cudaEventCreateWithFlags(&ev_join, cudaEventDisableTiming);
        cudaFuncSetAttribute(k_gemm, cudaFuncAttributeMaxDynamicSharedMemorySize,
                             GEMM_SMEM);
    }

    // fork: everything independent of h on s1; gemm on main stream
    cudaEventRecord(ev_fork, 0);
    cudaStreamWaitEvent(s1, ev_fork, 0);

    k_init<<<(N_NODES + 255) / 256, 256, 0, s1>>>((const unsigned int*)ei);
    k_wa<<<1, IN_F, 0, s1>>>(W, att_src, att_dst);
    k_attn<<<(N_NODES * 32 + 255) / 256, 256, 0, s1>>>(x);
    k_fill<<<(N_EDGES / 4 + 255) / 256, 256, 0, s1>>>(ei);

    k_gemm<<<(N_NODES + RPB - 1) / RPB, GT, GEMM_SMEM>>>(x, W);

    // join: aggr needs h (gemm) AND asrc/adst/slots/counts (s1)
    cudaEventRecord(ev_join, s1);
    cudaStreamWaitEvent(0, ev_join, 0);

    k_aggr<<<((size_t)N_NODES * 32 + 255) / 256, 256>>>(bias, out);
}